// round 15
// baseline (speedup 1.0000x reference)
#include <cuda_runtime.h>

#define N_PRED 20
#define N_LAB  12
#define QTR    5     // preds per thread (4 threads per row)

__device__ __forceinline__ float sqrt_approx(float x){ float r; asm("sqrt.approx.f32 %0,%1;":"=f"(r):"f"(x)); return r; }
__device__ __forceinline__ float log2_approx(float x){ float r; asm("lg2.approx.f32 %0,%1;":"=f"(r):"f"(x)); return r; }

__global__ __launch_bounds__(64, 20)
void myloss_kernel(const float4* __restrict__ pred,   // [B, 20, 4]
                   const float4* __restrict__ label,  // [B, 12, 4]
                   float* __restrict__ out, int B)
{
    int t = blockIdx.x * blockDim.x + threadIdx.x;
    int b = t >> 2;          // row
    int h = t & 3;           // quarter of the preds owned by this thread
    bool valid = (b < B);
    if (!valid) b = B - 1;   // keep warps converged for the shuffles

    // My 5 preds in registers (contiguous 80B -> coalesced float4 loads).
    float px[QTR], py[QTR], pz[QTR], pw[QTR];
    const float4* pr = pred + (long)b * N_PRED + h * QTR;
    #pragma unroll
    for (int j = 0; j < QTR; j++) {
        float4 v = pr[j];
        px[j] = v.x; py[j] = v.y; pz[j] = v.z; pw[j] = v.w;
    }

    const float4* lb = label + (long)b * N_LAB;
    float csum = 0.f;            // sum of winning keys (cost + <=31ulp idx noise)
    unsigned cnt = 0u;           // 4-bit match multiplicity per local pred (5 nibbles)
    const int gbase = QTR * h;   // my first global pred index
    const int g4    = 4 * gbase; // hoisted shift base

    #pragma unroll
    for (int l = 0; l < N_LAB; l++) {
        float4 y = lb[l];        // 4 lanes share the sector -> L1 broadcast

        // Keys: low 5 mantissa bits carry the GLOBAL pred index, so a plain
        // nonneg-float min is an exact lexicographic (cost, idx) min
        // == jnp.argmin first-min tie-break across all 20 preds.
        float m[QTR];
        #pragma unroll
        for (int j = 0; j < QTR; j++) {
            float dx = y.x - px[j], dy = y.y - py[j];
            float c  = sqrt_approx(fmaf(dx, dx, dy * dy)) + fabsf(y.z - pz[j]);
            m[j] = __uint_as_float((__float_as_uint(c) & 0xFFFFFFE0u) | (unsigned)(gbase + j));
        }
        float w  = fminf(fminf(fminf(m[0], m[1]), fminf(m[2], m[3])), m[4]);

        // 2-round butterfly merge across the 4 lanes of this row.
        float w1 = fminf(w,  __shfl_xor_sync(0xffffffffu, w,  1));
        float wc = fminf(w1, __shfl_xor_sync(0xffffffffu, w1, 2));

        // Raw key accumulate: idx bits add ~2e-6 relative noise total --
        // verified bit-identical rel_err vs stripped accumulate.
        csum += wc;
        if (__float_as_uint(wc) == __float_as_uint(w)) {   // unique keys:
            int sh = ((int)(__float_as_uint(w) & 31u) << 2) - g4;  // 4*local_j
            cnt += 1u << sh;                               // exactly one lane
        }
    }

    // Epilogue: exactly one log per pred.
    //   matched (n>0): -n*log(pw+eps)/12
    //   unmatched:     (-log(1-pw+eps) + 0.5*pz)*0.5/8
    const float EPS = 1e-6f;
    const float LN2 = 0.69314718055994530942f;
    float S = 0.f;
    #pragma unroll
    for (int j = 0; j < QTR; j++) {
        int n = (int)((cnt >> (4 * j)) & 15u);
        bool mt = (n > 0);
        float arg  = mt ? (pw[j] + EPS) : ((1.0f + EPS) - pw[j]);
        float lg   = log2_approx(arg);
        float coef = mt ? ((float)n) * (-LN2 / 12.0f) : (-LN2 / 16.0f);
        S = fmaf(coef, lg, S);
        if (!mt) S = fmaf(pz[j], 1.0f / 32.0f, S);
    }
    S += __shfl_xor_sync(0xffffffffu, S, 1);
    S += __shfl_xor_sync(0xffffffffu, S, 2);

    if (valid && h == 0)
        out[b] = fmaf(csum, 0.5f / 12.0f, S);
}

extern "C" void kernel_launch(void* const* d_in, const int* in_sizes, int n_in,
                              void* d_out, int out_size)
{
    const float4* pred  = (const float4*)d_in[0];
    const float4* label = (const float4*)d_in[1];
    float* out = (float*)d_out;
    int B = in_sizes[0] / (N_PRED * 4);

    long threads_total = 4L * B;
    int threads = 64;
    int blocks = (int)((threads_total + threads - 1) / threads);
    myloss_kernel<<<blocks, threads>>>(pred, label, out, B);
}